// round 2
// baseline (speedup 1.0000x reference)
#include <cuda_runtime.h>
#include <cuda_bf16.h>

#define N_NODES 100000
#define N_EDGES 1600000
#define D 32
#define ED 8

// Scratch (ping-pong node features + aggregation buffer).
__device__ float g_buf0[N_NODES * D];
__device__ float g_buf1[N_NODES * D];
__device__ float g_agg[N_NODES * D];

// ---------------------------------------------------------------------------
// Zero the aggregation buffer (only needed once, before layer 0; the node
// kernel re-zeroes agg for the next layer as it consumes it).
// ---------------------------------------------------------------------------
__global__ void zero_agg_kernel() {
    const int n4 = N_NODES * D / 4;
    float4* p = reinterpret_cast<float4*>(g_agg);
    float4 z = make_float4(0.f, 0.f, 0.f, 0.f);
    for (int i = blockIdx.x * blockDim.x + threadIdx.x; i < n4;
         i += gridDim.x * blockDim.x) {
        p[i] = z;
    }
}

// ---------------------------------------------------------------------------
// Edge kernel: 4 edges per warp per iteration.
//   lane layout: g = lane>>3 selects edge-in-quad, c = lane&7 selects a
//   column quad (columns 4c..4c+3).
// Per 4 edges:
//   - 1 coalesced LDG (128B) loads all 4 edges' 8 attrs
//   - 8 SHFLs distribute attrs within each 8-lane group
//   - 32 FMAs compute the edge embeddings (float4 per lane)
//   - 1 LDG.128 gathers x[src] rows (4 x 128B lines)
//   - 1 RED.128 (red.global.add.v4.f32) scatters into agg
// ---------------------------------------------------------------------------
__global__ __launch_bounds__(256) void edge_kernel(
    const float* __restrict__ x_ext, int x_sel,
    const float* __restrict__ edge_attr,
    const float* __restrict__ We,   // layer slice: [8, 32]
    const float* __restrict__ be,   // layer slice: [32]
    const int*   __restrict__ src,
    const int*   __restrict__ dst)
{
    const float* x = (x_sel == 0) ? x_ext : (x_sel == 1 ? g_buf0 : g_buf1);

    const int lane = threadIdx.x & 31;
    const int c    = lane & 7;    // column quad index
    const int g    = lane >> 3;   // edge within the 4-edge group
    const int wid  = (blockIdx.x * blockDim.x + threadIdx.x) >> 5;
    const int nw   = (gridDim.x * blockDim.x) >> 5;

    // We column quad for this lane: We[k][4c..4c+3], k = 0..7  (32 regs)
    float4 wv[ED];
#pragma unroll
    for (int k = 0; k < ED; k++)
        wv[k] = *reinterpret_cast<const float4*>(We + k * D + c * 4);
    const float4 bias = *reinterpret_cast<const float4*>(be + c * 4);

    for (int e4 = wid * 4; e4 < N_EDGES; e4 += nw * 4) {
        const int s = __ldg(src + e4 + g);
        const int d = __ldg(dst + e4 + g);
        // lane reads ea[(e4)*8 + lane] = edge (e4 + lane/8), attr (lane%8)
        const float av = __ldg(edge_attr + e4 * ED + lane);

        float4 acc = bias;
#pragma unroll
        for (int k = 0; k < ED; k++) {
            const float f = __shfl_sync(0xffffffffu, av, (g << 3) | k);
            acc.x = fmaf(f, wv[k].x, acc.x);
            acc.y = fmaf(f, wv[k].y, acc.y);
            acc.z = fmaf(f, wv[k].z, acc.z);
            acc.w = fmaf(f, wv[k].w, acc.w);
        }

        const float4 xv =
            __ldg(reinterpret_cast<const float4*>(x + s * D + c * 4));
        float4 m;
        m.x = fmaxf(xv.x + acc.x, 0.0f);
        m.y = fmaxf(xv.y + acc.y, 0.0f);
        m.z = fmaxf(xv.z + acc.z, 0.0f);
        m.w = fmaxf(xv.w + acc.w, 0.0f);

        float* p = g_agg + d * D + c * 4;
        asm volatile("red.global.add.v4.f32 [%0], {%1,%2,%3,%4};"
                     :: "l"(p), "f"(m.x), "f"(m.y), "f"(m.z), "f"(m.w)
                     : "memory");
    }
}

// ---------------------------------------------------------------------------
// Node kernel: one warp per node, lane = output column j.
//   h_k  = x[node][k] + agg[node][k];  agg is re-zeroed for the next layer.
//   o_j  = leaky_relu(b[j] + sum_k h_k * W[k][j])
// ---------------------------------------------------------------------------
__global__ __launch_bounds__(256) void node_kernel(
    const float* __restrict__ x_ext, int x_sel,
    float* __restrict__ out_ext, int out_sel,
    const float* __restrict__ W,    // layer slice: [32, 32]
    const float* __restrict__ b)    // layer slice: [32]
{
    const float* x  = (x_sel == 0) ? x_ext : (x_sel == 1 ? g_buf0 : g_buf1);
    float* out = (out_sel == 0) ? out_ext : (out_sel == 1 ? g_buf0 : g_buf1);

    const int lane = threadIdx.x & 31;
    const int wid  = (blockIdx.x * blockDim.x + threadIdx.x) >> 5;
    const int nw   = (gridDim.x * blockDim.x) >> 5;

    float w[D];
#pragma unroll
    for (int k = 0; k < D; k++) w[k] = W[k * D + lane];
    const float bias = b[lane];

    for (int node = wid; node < N_NODES; node += nw) {
        const float a = g_agg[node * D + lane];
        const float h = x[node * D + lane] + a;
        g_agg[node * D + lane] = 0.0f;   // pre-zero for next layer
        float acc = bias;
#pragma unroll
        for (int k = 0; k < D; k++)
            acc = fmaf(__shfl_sync(0xffffffffu, h, k), w[k], acc);
        out[node * D + lane] = fmaxf(acc, 0.01f * acc);  // leaky_relu 0.01
    }
}

// ---------------------------------------------------------------------------
// 3 layers of { edge scatter; node transform }. agg zeroed once up front,
// then recycled by node_kernel. Ping-pong: ext -> g_buf0 -> g_buf1 -> d_out.
// ---------------------------------------------------------------------------
extern "C" void kernel_launch(void* const* d_in, const int* in_sizes, int n_in,
                              void* d_out, int out_size)
{
    const float* x   = (const float*)d_in[0];   // [N, 32]
    const float* ea  = (const float*)d_in[1];   // [E, 8]
    const float* W   = (const float*)d_in[2];   // [3, 32, 32]
    const float* b   = (const float*)d_in[3];   // [3, 32]
    const float* We  = (const float*)d_in[4];   // [3, 8, 32]
    const float* be  = (const float*)d_in[5];   // [3, 32]
    const int*   ei  = (const int*)d_in[6];     // [2, E] int32
    float* out = (float*)d_out;

    const int* src = ei;
    const int* dst = ei + N_EDGES;

    const int x_sels[3]   = {0, 1, 2};
    const int out_sels[3] = {1, 2, 0};

    const int edge_blocks = 1184;   // 148 SMs * 8
    const int node_blocks = 592;

    zero_agg_kernel<<<1184, 256>>>();
    for (int l = 0; l < 3; l++) {
        edge_kernel<<<edge_blocks, 256>>>(
            x, x_sels[l], ea, We + l * ED * D, be + l * D, src, dst);
        node_kernel<<<node_blocks, 256>>>(
            x, x_sels[l], out, out_sels[l], W + l * D * D, b + l * D);
    }
}